// round 1
// baseline (speedup 1.0000x reference)
#include <cuda_runtime.h>

// 2D Haar DWT, fp32, x:[16,64,512,512] -> out:[4,16,64,256,256]
// Pure streaming: 1 GiB in + 1 GiB out. DRAM-bound.
//
// Per output pixel (h,w), block = [[a,b],[c,d]] with a=x[2h,2w], b=x[2h,2w+1],
// c=x[2h+1,2w], d=x[2h+1,2w+1]. With lo=[r,r], hi=[r,-r], r=1/sqrt(2):
//   ll = 0.5*(a+b+c+d)
//   lh = 0.5*(a+b-c-d)   (hi on row index p)
//   hl = 0.5*(a-b+c-d)   (hi on col index q)
//   hh = 0.5*(a-b-c+d)
//
// One thread handles 4 output columns: two float4 loads per input row
// (2 rows), one float4 store per band. All accesses 16B, warp-contiguous.

static constexpr int W_IN  = 512;
static constexpr int H_IN  = 512;
static constexpr int W_OUT = 256;
static constexpr int H_OUT = 256;
static constexpr int PLANES = 16 * 64;               // B*C = 1024
static constexpr long long OUT_PLANE = (long long)W_OUT * H_OUT;       // 65536
static constexpr long long BAND_STRIDE = (long long)PLANES * OUT_PLANE; // 67,108,864

__global__ __launch_bounds__(256) void haar_dwt_kernel(
    const float* __restrict__ x, float* __restrict__ out)
{
    unsigned idx = blockIdx.x * 256u + threadIdx.x;   // 0 .. 16,777,215
    unsigned tx = idx & 63u;          // 4-col group within row (64 groups * 4 = 256 cols)
    unsigned h  = (idx >> 6) & 255u;  // output row
    unsigned p  = idx >> 14;          // plane 0..1023

    // Input: row 2h and 2h+1 of plane p, 8 consecutive floats starting at col 8*tx.
    const float* base = x + (size_t)p * (W_IN * H_IN) + (size_t)(2u * h) * W_IN + tx * 8u;
    float4 r0a = *reinterpret_cast<const float4*>(base);
    float4 r0b = *reinterpret_cast<const float4*>(base + 4);
    float4 r1a = *reinterpret_cast<const float4*>(base + W_IN);
    float4 r1b = *reinterpret_cast<const float4*>(base + W_IN + 4);

    float4 ll, lh, hl, hh;

    // col 0: a=r0a.x b=r0a.y c=r1a.x d=r1a.y
    {
        float sT = r0a.x + r0a.y, dT = r0a.x - r0a.y;
        float sB = r1a.x + r1a.y, dB = r1a.x - r1a.y;
        ll.x = 0.5f * (sT + sB); lh.x = 0.5f * (sT - sB);
        hl.x = 0.5f * (dT + dB); hh.x = 0.5f * (dT - dB);
    }
    // col 1: r0a.z r0a.w / r1a.z r1a.w
    {
        float sT = r0a.z + r0a.w, dT = r0a.z - r0a.w;
        float sB = r1a.z + r1a.w, dB = r1a.z - r1a.w;
        ll.y = 0.5f * (sT + sB); lh.y = 0.5f * (sT - sB);
        hl.y = 0.5f * (dT + dB); hh.y = 0.5f * (dT - dB);
    }
    // col 2: r0b.x r0b.y / r1b.x r1b.y
    {
        float sT = r0b.x + r0b.y, dT = r0b.x - r0b.y;
        float sB = r1b.x + r1b.y, dB = r1b.x - r1b.y;
        ll.z = 0.5f * (sT + sB); lh.z = 0.5f * (sT - sB);
        hl.z = 0.5f * (dT + dB); hh.z = 0.5f * (dT - dB);
    }
    // col 3: r0b.z r0b.w / r1b.z r1b.w
    {
        float sT = r0b.z + r0b.w, dT = r0b.z - r0b.w;
        float sB = r1b.z + r1b.w, dB = r1b.z - r1b.w;
        ll.w = 0.5f * (sT + sB); lh.w = 0.5f * (sT - sB);
        hl.w = 0.5f * (dT + dB); hh.w = 0.5f * (dT - dB);
    }

    float* o = out + (size_t)p * OUT_PLANE + (size_t)h * W_OUT + tx * 4u;
    *reinterpret_cast<float4*>(o)                   = ll;
    *reinterpret_cast<float4*>(o + BAND_STRIDE)     = lh;
    *reinterpret_cast<float4*>(o + 2 * BAND_STRIDE) = hl;
    *reinterpret_cast<float4*>(o + 3 * BAND_STRIDE) = hh;
}

extern "C" void kernel_launch(void* const* d_in, const int* in_sizes, int n_in,
                              void* d_out, int out_size) {
    const float* x = (const float*)d_in[0];
    float* out = (float*)d_out;
    // total threads = 1024 planes * 256 rows * 64 groups = 16,777,216
    unsigned total = (unsigned)PLANES * H_OUT * (W_OUT / 4);
    haar_dwt_kernel<<<total / 256, 256>>>(x, out);
}